// round 3
// baseline (speedup 1.0000x reference)
#include <cuda_runtime.h>
#include <math.h>

#define NN 100000
#define NG 64
#define D  128

// -------- scratch (device globals; no runtime allocation) --------
__device__ float g_h  [(size_t)NN * D];   // GEMM output (pre-aggregation features)
__device__ float g_agg[(size_t)NN * D];   // aggregated layer output
__device__ float g_dinv[NN];              // degree -> d^{-1/2}
__device__ float g_pool[NG * D];
__device__ float g_cnt [NG];

// ---------------- degree / normalization ----------------
__global__ void k_deg_init() {
    int i = blockIdx.x * blockDim.x + threadIdx.x;
    if (i < NN) g_dinv[i] = 1.0f;              // self loop
}

__global__ void k_deg_edges(const int* __restrict__ ei, int E) {
    int e = blockIdx.x * blockDim.x + threadIdx.x;
    if (e >= E) return;
    unsigned dst = (unsigned)ei[(size_t)E + e];   // dst = col
    if (dst < NN) atomicAdd(&g_dinv[dst], 1.0f);
}

__global__ void k_rsqrt() {
    int i = blockIdx.x * blockDim.x + threadIdx.x;
    if (i < NN) g_dinv[i] = rsqrtf(g_dinv[i]);
}

// ---------------- GEMM: H = X @ W  (warp per row) ----------------
__device__ __forceinline__ void gemm_row(const float* __restrict__ X,
                                         const float* __restrict__ W,
                                         int row, int lane) {
    const float4* x4 = (const float4*)(X + (size_t)row * D);
    const float*  wc = W + lane * 4;
    float a0 = 0.f, a1 = 0.f, a2 = 0.f, a3 = 0.f;
#pragma unroll
    for (int k4 = 0; k4 < D / 4; k4++) {
        float4 xv = __ldg(&x4[k4]);
        int k = k4 * 4;
        float4 w;
        w = __ldg((const float4*)(wc + (size_t)(k + 0) * D));
        a0 = fmaf(xv.x, w.x, a0); a1 = fmaf(xv.x, w.y, a1);
        a2 = fmaf(xv.x, w.z, a2); a3 = fmaf(xv.x, w.w, a3);
        w = __ldg((const float4*)(wc + (size_t)(k + 1) * D));
        a0 = fmaf(xv.y, w.x, a0); a1 = fmaf(xv.y, w.y, a1);
        a2 = fmaf(xv.y, w.z, a2); a3 = fmaf(xv.y, w.w, a3);
        w = __ldg((const float4*)(wc + (size_t)(k + 2) * D));
        a0 = fmaf(xv.z, w.x, a0); a1 = fmaf(xv.z, w.y, a1);
        a2 = fmaf(xv.z, w.z, a2); a3 = fmaf(xv.z, w.w, a3);
        w = __ldg((const float4*)(wc + (size_t)(k + 3) * D));
        a0 = fmaf(xv.w, w.x, a0); a1 = fmaf(xv.w, w.y, a1);
        a2 = fmaf(xv.w, w.z, a2); a3 = fmaf(xv.w, w.w, a3);
    }
    ((float4*)(g_h + (size_t)row * D))[lane] = make_float4(a0, a1, a2, a3);
}

__global__ void k_gemm_x(const float* __restrict__ X, const float* __restrict__ W) {
    int warp = (blockIdx.x * blockDim.x + threadIdx.x) >> 5;
    int lane = threadIdx.x & 31;
    if (warp >= NN) return;
    gemm_row(X, W, warp, lane);
}

// layer 2: input is g_agg (already ELU'd in place)
__global__ void k_gemm_agg(const float* __restrict__ W) {
    int warp = (blockIdx.x * blockDim.x + threadIdx.x) >> 5;
    int lane = threadIdx.x & 31;
    if (warp >= NN) return;
    gemm_row(g_agg, W, warp, lane);
}

// ---------------- aggregation ----------------
// init: out = bias + dinv^2 * h   (self-loop term)
__global__ void k_agg_init(const float* __restrict__ b) {
    int idx = blockIdx.x * blockDim.x + threadIdx.x;
    if (idx >= NN * D) return;
    int i = idx >> 7;
    int f = idx & (D - 1);
    float dv = g_dinv[i];
    g_agg[idx] = b[f] + dv * dv * g_h[idx];
}

// edges: out[dst] += h[src] * dinv[src]*dinv[dst]   (warp per edge)
__global__ void k_agg_edges(const int* __restrict__ ei, int E) {
    int e = (blockIdx.x * blockDim.x + threadIdx.x) >> 5;
    int lane = threadIdx.x & 31;
    if (e >= E) return;
    unsigned src = (unsigned)ei[e];
    unsigned dst = (unsigned)ei[(size_t)E + e];
    if (src >= NN || dst >= NN) return;
    float norm = g_dinv[src] * g_dinv[dst];
    float4 v = __ldg((const float4*)(g_h + (size_t)src * D) + lane);
    float* o = g_agg + (size_t)dst * D + lane * 4;
    atomicAdd(o + 0, v.x * norm);
    atomicAdd(o + 1, v.y * norm);
    atomicAdd(o + 2, v.z * norm);
    atomicAdd(o + 3, v.w * norm);
}

// ---------------- ELU (in place on g_agg) ----------------
__global__ void k_elu() {
    int idx = blockIdx.x * blockDim.x + threadIdx.x;
    if (idx >= NN * D) return;
    float v = g_agg[idx];
    g_agg[idx] = v > 0.f ? v : expm1f(v);
}

// ---------------- pooling ----------------
__global__ void k_zero_pool() {
    int i = blockIdx.x * blockDim.x + threadIdx.x;
    if (i < NG * D) g_pool[i] = 0.f;
    if (i < NG) g_cnt[i] = 0.f;
}

#define NPB 256  // nodes per block
__global__ void k_pool(const int* __restrict__ batch) {
    int f = threadIdx.x;             // 128 threads, one per feature
    int start = blockIdx.x * NPB;
    if (start >= NN) return;
    int end = start + NPB; if (end > NN) end = NN;

    float acc = 0.f;
    int cur = batch[start];
    if ((unsigned)cur >= NG) cur = 0;
    for (int n = start; n < end; n++) {
        int b = batch[n];
        if ((unsigned)b >= NG) b = 0;
        if (b != cur) {
            atomicAdd(&g_pool[cur * D + f], acc);
            acc = 0.f; cur = b;
        }
        acc += g_agg[(size_t)n * D + f];
    }
    atomicAdd(&g_pool[cur * D + f], acc);

    if (f == 0) {
        float c = 0.f;
        int cur2 = batch[start];
        if ((unsigned)cur2 >= NG) cur2 = 0;
        for (int n = start; n < end; n++) {
            int b = batch[n];
            if ((unsigned)b >= NG) b = 0;
            if (b != cur2) { atomicAdd(&g_cnt[cur2], c); c = 0.f; cur2 = b; }
            c += 1.0f;
        }
        atomicAdd(&g_cnt[cur2], c);
    }
}

// ---------------- final MLP + log_softmax (block per graph) ----------------
__global__ void k_mlp(const float* __restrict__ fc1W, const float* __restrict__ fc1b,
                      const float* __restrict__ fc2W, const float* __restrict__ fc2b,
                      float* __restrict__ out) {
    int g = blockIdx.x;
    int lane = threadIdx.x;   // 32 threads
    __shared__ float mean[D];
    __shared__ float m1[20];
    __shared__ float z[10];
    __shared__ float lse;

    float cnt = fmaxf(g_cnt[g], 1.0f);
    for (int k = lane; k < D; k += 32) mean[k] = g_pool[g * D + k] / cnt;
    __syncwarp();

    if (lane < 20) {
        float s = fc1b[lane];
        for (int k = 0; k < D; k++) s = fmaf(mean[k], fc1W[k * 20 + lane], s);
        m1[lane] = fmaxf(s, 0.0f);   // relu
    }
    __syncwarp();

    if (lane < 10) {
        float s = fc2b[lane];
        for (int k = 0; k < 20; k++) s = fmaf(m1[k], fc2W[k * 10 + lane], s);
        z[lane] = s;
    }
    __syncwarp();

    if (lane == 0) {
        float mx = z[0];
        for (int j = 1; j < 10; j++) mx = fmaxf(mx, z[j]);
        float s = 0.f;
        for (int j = 0; j < 10; j++) s += expf(z[j] - mx);
        lse = mx + logf(s);
    }
    __syncwarp();

    if (lane < 10) out[g * 10 + lane] = z[lane] - lse;
}

// ---------------- launch ----------------
extern "C" void kernel_launch(void* const* d_in, const int* in_sizes, int n_in,
                              void* d_out, int out_size) {
    // ---- size-based input resolution (robust to metadata ordering) ----
    int ix = -1, iei = -1, ib = -1, iW[2] = {-1, -1}, ibias[2] = {-1, -1};
    int if1W = -1, if1b = -1, if2W = -1, if2b = -1;
    int nW = 0, nbias = 0;
    for (int i = 0; i < n_in; i++) {
        int s = in_sizes[i];
        if      (s == NN * D)            ix = i;
        else if (s == NN)                ib = i;
        else if (s == D * D && nW < 2)   iW[nW++] = i;
        else if (s == D && nbias < 2)    ibias[nbias++] = i;
        else if (s == D * 20)            if1W = i;
        else if (s == 20)                if1b = i;
        else if (s == 20 * 10)           if2W = i;
        else if (s == 10)                if2b = i;
        else if (s > NN)                 iei = i;   // edge_index (2*E)
    }
    bool ok = (ix >= 0 && iei >= 0 && ib >= 0 && nW == 2 && nbias == 2 &&
               if1W >= 0 && if1b >= 0 && if2W >= 0 && if2b >= 0);
    if (!ok) {  // fall back to positional (setup_inputs dict order)
        ix = 0; iei = 1; ib = 2; iW[0] = 3; ibias[0] = 4; iW[1] = 5; ibias[1] = 6;
        if1W = 7; if1b = 8; if2W = 9; if2b = 10;
    }

    const float* x     = (const float*)d_in[ix];
    const int*   ei    = (const int*)d_in[iei];     // int32 per harness dtype rules
    const int*   batch = (const int*)d_in[ib];      // int32
    const float* W1   = (const float*)d_in[iW[0]];
    const float* b1   = (const float*)d_in[ibias[0]];
    const float* W2   = (const float*)d_in[iW[1]];
    const float* b2   = (const float*)d_in[ibias[1]];
    const float* fc1W = (const float*)d_in[if1W];
    const float* fc1b = (const float*)d_in[if1b];
    const float* fc2W = (const float*)d_in[if2W];
    const float* fc2b = (const float*)d_in[if2b];
    float* out = (float*)d_out;

    int E = in_sizes[iei] / 2;

    const int T = 256;
    int nb_nodes = (NN + T - 1) / T;
    int nb_edges = (E + T - 1) / T;
    int nb_feat  = (NN * D + T - 1) / T;
    int nb_gemm  = (NN * 32 + T - 1) / T;                    // warp per row
    int nb_eagg  = (int)(((size_t)E * 32 + T - 1) / T);      // warp per edge
    int nb_pool  = (NN + NPB - 1) / NPB;

    // degree / normalization (shared by both layers)
    k_deg_init<<<nb_nodes, T>>>();
    k_deg_edges<<<nb_edges, T>>>(ei, E);
    k_rsqrt<<<nb_nodes, T>>>();

    // layer 1: h = x@W1 ; agg ; elu
    k_gemm_x<<<nb_gemm, T>>>(x, W1);
    k_agg_init<<<nb_feat, T>>>(b1);
    k_agg_edges<<<nb_eagg, T>>>(ei, E);
    k_elu<<<nb_feat, T>>>();

    // layer 2: h = elu_out@W2 ; agg
    k_gemm_agg<<<nb_gemm, T>>>(W2);
    k_agg_init<<<nb_feat, T>>>(b2);
    k_agg_edges<<<nb_eagg, T>>>(ei, E);

    // pool + mlp + log_softmax
    k_zero_pool<<<(NG * D + T - 1) / T, T>>>();
    k_pool<<<nb_pool, D>>>(batch);
    k_mlp<<<NG, 32>>>(fc1W, fc1b, fc2W, fc2b, out);
}

// round 5
// speedup vs baseline: 1.8745x; 1.8745x over previous
#include <cuda_runtime.h>
#include <math.h>

#define NN 100000
#define NG 64
#define D  128

// -------- scratch (device globals; no runtime allocation) --------
__device__ float g_h  [(size_t)NN * D];   // GEMM output (pre-aggregation features)
__device__ float g_agg[(size_t)NN * D];   // aggregated layer output
__device__ float g_elu[(size_t)NN * D];   // ELU(layer1 agg) = input to layer 2 GEMM
__device__ float g_dinv[NN];              // degree -> d^{-1/2}
__device__ float g_pool[NG * D];
__device__ float g_cnt [NG];

// ---------------- degree / normalization ----------------
__global__ void k_deg_init() {
    int i = blockIdx.x * blockDim.x + threadIdx.x;
    if (i < NN) g_dinv[i] = 1.0f;              // self loop
}

__global__ void k_deg_edges(const int* __restrict__ ei, int E) {
    int e = blockIdx.x * blockDim.x + threadIdx.x;
    if (e >= E) return;
    unsigned dst = (unsigned)ei[(size_t)E + e];   // dst = col
    if (dst < NN) atomicAdd(&g_dinv[dst], 1.0f);
}

__global__ void k_rsqrt() {
    int i = blockIdx.x * blockDim.x + threadIdx.x;
    if (i < NN) g_dinv[i] = rsqrtf(g_dinv[i]);
}

// ---------------- tiled GEMM: H = X @ W  + fused self-loop epilogue ------
// BM=64 rows/block, full N=128, BK=64. 256 threads, thread tile 4Mx8N.
// Epilogue: g_h[row] = h ; g_agg[row] = bias + dinv[row]^2 * h
#define BM 64
#define BK 64

__device__ __forceinline__
void gemm_body(const float* __restrict__ X, const float* __restrict__ W,
               const float* __restrict__ bias) {
    __shared__ float sW[BK][128];   // 32 KB  (W tile, [k][n])
    __shared__ float sX[BM][BK];    // 16 KB  (X tile, [m][k])

    int tid = threadIdx.x;
    int tm  = tid >> 4;          // 0..15 -> rows  tm*4 .. tm*4+3
    int tn  = tid & 15;          // 0..15 -> cols  tn*8 .. tn*8+7
    int m0  = blockIdx.x * BM;

    float acc[4][8];
#pragma unroll
    for (int i = 0; i < 4; i++)
#pragma unroll
        for (int j = 0; j < 8; j++) acc[i][j] = 0.f;

    for (int kt = 0; kt < D; kt += BK) {
        // load W tile: 64x128 floats contiguous
        {
            const float4* Wg = (const float4*)(W + (size_t)kt * D);
            float4* sWv = (float4*)&sW[0][0];
#pragma unroll
            for (int i = 0; i < 8; i++)
                sWv[tid + 256 * i] = __ldg(&Wg[tid + 256 * i]);
        }
        // load X tile: 64 rows x 64 cols (guard tail rows with zeros)
        {
#pragma unroll
            for (int i = 0; i < 4; i++) {
                int idx = tid + 256 * i;      // 0..1023
                int r   = idx >> 4;           // 0..63
                int c4  = idx & 15;           // float4 within row
                float4 v = make_float4(0.f, 0.f, 0.f, 0.f);
                int row = m0 + r;
                if (row < NN)
                    v = __ldg((const float4*)(X + (size_t)row * D + kt) + c4);
                *(float4*)&sX[r][c4 * 4] = v;
            }
        }
        __syncthreads();

#pragma unroll 8
        for (int k = 0; k < BK; k++) {
            float a0 = sX[tm * 4 + 0][k];
            float a1 = sX[tm * 4 + 1][k];
            float a2 = sX[tm * 4 + 2][k];
            float a3 = sX[tm * 4 + 3][k];
            float4 b0 = *(float4*)&sW[k][tn * 8];
            float4 b1 = *(float4*)&sW[k][tn * 8 + 4];
            acc[0][0] = fmaf(a0, b0.x, acc[0][0]); acc[0][1] = fmaf(a0, b0.y, acc[0][1]);
            acc[0][2] = fmaf(a0, b0.z, acc[0][2]); acc[0][3] = fmaf(a0, b0.w, acc[0][3]);
            acc[0][4] = fmaf(a0, b1.x, acc[0][4]); acc[0][5] = fmaf(a0, b1.y, acc[0][5]);
            acc[0][6] = fmaf(a0, b1.z, acc[0][6]); acc[0][7] = fmaf(a0, b1.w, acc[0][7]);
            acc[1][0] = fmaf(a1, b0.x, acc[1][0]); acc[1][1] = fmaf(a1, b0.y, acc[1][1]);
            acc[1][2] = fmaf(a1, b0.z, acc[1][2]); acc[1][3] = fmaf(a1, b0.w, acc[1][3]);
            acc[1][4] = fmaf(a1, b1.x, acc[1][4]); acc[1][5] = fmaf(a1, b1.y, acc[1][5]);
            acc[1][6] = fmaf(a1, b1.z, acc[1][6]); acc[1][7] = fmaf(a1, b1.w, acc[1][7]);
            acc[2][0] = fmaf(a2, b0.x, acc[2][0]); acc[2][1] = fmaf(a2, b0.y, acc[2][1]);
            acc[2][2] = fmaf(a2, b0.z, acc[2][2]); acc[2][3] = fmaf(a2, b0.w, acc[2][3]);
            acc[2][4] = fmaf(a2, b1.x, acc[2][4]); acc[2][5] = fmaf(a2, b1.y, acc[2][5]);
            acc[2][6] = fmaf(a2, b1.z, acc[2][6]); acc[2][7] = fmaf(a2, b1.w, acc[2][7]);
            acc[3][0] = fmaf(a3, b0.x, acc[3][0]); acc[3][1] = fmaf(a3, b0.y, acc[3][1]);
            acc[3][2] = fmaf(a3, b0.z, acc[3][2]); acc[3][3] = fmaf(a3, b0.w, acc[3][3]);
            acc[3][4] = fmaf(a3, b1.x, acc[3][4]); acc[3][5] = fmaf(a3, b1.y, acc[3][5]);
            acc[3][6] = fmaf(a3, b1.z, acc[3][6]); acc[3][7] = fmaf(a3, b1.w, acc[3][7]);
        }
        __syncthreads();
    }

    // epilogue: write h and agg = bias + dinv^2 * h
    float4 bb0 = __ldg((const float4*)(bias + tn * 8));
    float4 bb1 = __ldg((const float4*)(bias + tn * 8 + 4));
#pragma unroll
    for (int i = 0; i < 4; i++) {
        int row = m0 + tm * 4 + i;
        if (row >= NN) break;
        float dv  = g_dinv[row];
        float dv2 = dv * dv;
        float4 h0 = make_float4(acc[i][0], acc[i][1], acc[i][2], acc[i][3]);
        float4 h1 = make_float4(acc[i][4], acc[i][5], acc[i][6], acc[i][7]);
        float* hp = g_h + (size_t)row * D + tn * 8;
        *(float4*)(hp)     = h0;
        *(float4*)(hp + 4) = h1;
        float4 g0 = make_float4(bb0.x + dv2 * h0.x, bb0.y + dv2 * h0.y,
                                bb0.z + dv2 * h0.z, bb0.w + dv2 * h0.w);
        float4 g1 = make_float4(bb1.x + dv2 * h1.x, bb1.y + dv2 * h1.y,
                                bb1.z + dv2 * h1.z, bb1.w + dv2 * h1.w);
        float* gp = g_agg + (size_t)row * D + tn * 8;
        *(float4*)(gp)     = g0;
        *(float4*)(gp + 4) = g1;
    }
}

// layer 1: X comes from harness input (legal host pointer)
__global__ __launch_bounds__(256, 1)
void k_gemm_l1(const float* __restrict__ X, const float* __restrict__ W,
               const float* __restrict__ bias) {
    gemm_body(X, W, bias);
}

// layer 2: X = g_elu, referenced in DEVICE code (never passed from host)
__global__ __launch_bounds__(256, 1)
void k_gemm_l2(const float* __restrict__ W, const float* __restrict__ bias) {
    gemm_body(g_elu, W, bias);
}

// ---------------- edge aggregation: warp per edge, vector red ------------
__global__ void k_agg_edges(const int* __restrict__ ei, int E) {
    int e = (blockIdx.x * blockDim.x + threadIdx.x) >> 5;
    int lane = threadIdx.x & 31;
    if (e >= E) return;
    unsigned src = (unsigned)ei[e];
    unsigned dst = (unsigned)ei[(size_t)E + e];
    if (src >= NN || dst >= NN) return;
    float norm = g_dinv[src] * g_dinv[dst];
    float4 v = __ldg((const float4*)(g_h + (size_t)src * D) + lane);
    float* o = g_agg + (size_t)dst * D + lane * 4;
    asm volatile("red.global.add.v4.f32 [%0], {%1, %2, %3, %4};"
                 :: "l"(o), "f"(v.x * norm), "f"(v.y * norm),
                    "f"(v.z * norm), "f"(v.w * norm)
                 : "memory");
}

// ---------------- ELU: g_elu = elu(g_agg), float4 ----------------
__global__ void k_elu() {
    int idx = blockIdx.x * blockDim.x + threadIdx.x;
    if (idx >= NN * D / 4) return;
    float4 v = ((const float4*)g_agg)[idx];
    v.x = v.x > 0.f ? v.x : expm1f(v.x);
    v.y = v.y > 0.f ? v.y : expm1f(v.y);
    v.z = v.z > 0.f ? v.z : expm1f(v.z);
    v.w = v.w > 0.f ? v.w : expm1f(v.w);
    ((float4*)g_elu)[idx] = v;
}

// ---------------- pooling ----------------
__global__ void k_zero_pool() {
    int i = blockIdx.x * blockDim.x + threadIdx.x;
    if (i < NG * D) g_pool[i] = 0.f;
    if (i < NG) g_cnt[i] = 0.f;
}

#define NPB 256  // nodes per block
__global__ void k_pool(const int* __restrict__ batch) {
    int f = threadIdx.x;             // 128 threads, one per feature
    int start = blockIdx.x * NPB;
    if (start >= NN) return;
    int end = start + NPB; if (end > NN) end = NN;

    float acc = 0.f;
    int cur = batch[start];
    if ((unsigned)cur >= NG) cur = 0;
    for (int n = start; n < end; n++) {
        int b = batch[n];
        if ((unsigned)b >= NG) b = 0;
        if (b != cur) {
            atomicAdd(&g_pool[cur * D + f], acc);
            acc = 0.f; cur = b;
        }
        acc += g_agg[(size_t)n * D + f];
    }
    atomicAdd(&g_pool[cur * D + f], acc);

    if (f == 0) {
        float c = 0.f;
        int cur2 = batch[start];
        if ((unsigned)cur2 >= NG) cur2 = 0;
        for (int n = start; n < end; n++) {
            int b = batch[n];
            if ((unsigned)b >= NG) b = 0;
            if (b != cur2) { atomicAdd(&g_cnt[cur2], c); c = 0.f; cur2 = b; }
            c += 1.0f;
        }
        atomicAdd(&g_cnt[cur2], c);
    }
}

// ---------------- final MLP + log_softmax (block per graph) ----------------
__global__ void k_mlp(const float* __restrict__ fc1W, const float* __restrict__ fc1b,
                      const float* __restrict__ fc2W, const float* __restrict__ fc2b,
                      float* __restrict__ out) {
    int g = blockIdx.x;
    int lane = threadIdx.x;   // 32 threads
    __shared__ float mean[D];
    __shared__ float m1[20];
    __shared__ float z[10];
    __shared__ float lse;

    float cnt = fmaxf(g_cnt[g], 1.0f);
    for (int k = lane; k < D; k += 32) mean[k] = g_pool[g * D + k] / cnt;
    __syncwarp();

    if (lane < 20) {
        float s = fc1b[lane];
        for (int k = 0; k < D; k++) s = fmaf(mean[k], fc1W[k * 20 + lane], s);
        m1[lane] = fmaxf(s, 0.0f);   // relu
    }
    __syncwarp();

    if (lane < 10) {
        float s = fc2b[lane];
        for (int k = 0; k < 20; k++) s = fmaf(m1[k], fc2W[k * 10 + lane], s);
        z[lane] = s;
    }
    __syncwarp();

    if (lane == 0) {
        float mx = z[0];
        for (int j = 1; j < 10; j++) mx = fmaxf(mx, z[j]);
        float s = 0.f;
        for (int j = 0; j < 10; j++) s += expf(z[j] - mx);
        lse = mx + logf(s);
    }
    __syncwarp();

    if (lane < 10) out[g * 10 + lane] = z[lane] - lse;
}

// ---------------- launch ----------------
extern "C" void kernel_launch(void* const* d_in, const int* in_sizes, int n_in,
                              void* d_out, int out_size) {
    // ---- size-based input resolution (robust to metadata ordering) ----
    int ix = -1, iei = -1, ib = -1, iW[2] = {-1, -1}, ibias[2] = {-1, -1};
    int if1W = -1, if1b = -1, if2W = -1, if2b = -1;
    int nW = 0, nbias = 0;
    for (int i = 0; i < n_in; i++) {
        int s = in_sizes[i];
        if      (s == NN * D)            ix = i;
        else if (s == NN)                ib = i;
        else if (s == D * D && nW < 2)   iW[nW++] = i;
        else if (s == D && nbias < 2)    ibias[nbias++] = i;
        else if (s == D * 20)            if1W = i;
        else if (s == 20)                if1b = i;
        else if (s == 20 * 10)           if2W = i;
        else if (s == 10)                if2b = i;
        else if (s > NN)                 iei = i;   // edge_index (2*E)
    }
    bool ok = (ix >= 0 && iei >= 0 && ib >= 0 && nW == 2 && nbias == 2 &&
               if1W >= 0 && if1b >= 0 && if2W >= 0 && if2b >= 0);
    if (!ok) {  // fall back to positional (setup_inputs dict order)
        ix = 0; iei = 1; ib = 2; iW[0] = 3; ibias[0] = 4; iW[1] = 5; ibias[1] = 6;
        if1W = 7; if1b = 8; if2W = 9; if2b = 10;
    }

    const float* x     = (const float*)d_in[ix];
    const int*   ei    = (const int*)d_in[iei];     // int32
    const int*   batch = (const int*)d_in[ib];      // int32
    const float* W1   = (const float*)d_in[iW[0]];
    const float* b1   = (const float*)d_in[ibias[0]];
    const float* W2   = (const float*)d_in[iW[1]];
    const float* b2   = (const float*)d_in[ibias[1]];
    const float* fc1W = (const float*)d_in[if1W];
    const float* fc1b = (const float*)d_in[if1b];
    const float* fc2W = (const float*)d_in[if2W];
    const float* fc2b = (const float*)d_in[if2b];
    float* out = (float*)d_out;

    int E = in_sizes[iei] / 2;

    const int T = 256;
    int nb_nodes = (NN + T - 1) / T;
    int nb_edges = (E + T - 1) / T;
    int nb_gemm  = (NN + BM - 1) / BM;
    int nb_eagg  = (int)(((size_t)E * 32 + T - 1) / T);      // warp per edge
    int nb_elu   = (NN * D / 4 + T - 1) / T;
    int nb_pool  = (NN + NPB - 1) / NPB;

    // degree / normalization (shared by both layers)
    k_deg_init<<<nb_nodes, T>>>();
    k_deg_edges<<<nb_edges, T>>>(ei, E);
    k_rsqrt<<<nb_nodes, T>>>();

    // layer 1: h = x@W1 (epilogue inits agg) ; edge agg ; elu -> g_elu
    k_gemm_l1<<<nb_gemm, 256>>>(x, W1, b1);
    k_agg_edges<<<nb_eagg, T>>>(ei, E);
    k_elu<<<nb_elu, T>>>();

    // layer 2: h = g_elu@W2 ; edge agg
    k_gemm_l2<<<nb_gemm, 256>>>(W2, b2);
    k_agg_edges<<<nb_eagg, T>>>(ei, E);

    // pool + mlp + log_softmax
    k_zero_pool<<<(NG * D + T - 1) / T, T>>>();
    k_pool<<<nb_pool, D>>>(batch);
    k_mlp<<<NG, 32>>>(fc1W, fc1b, fc2W, fc2b, out);
}

// round 6
// speedup vs baseline: 2.2015x; 1.1744x over previous
#include <cuda_runtime.h>
#include <math.h>

#define NN 100000
#define NG 64
#define D  128
#define EMAX 2000000

// -------- scratch (device globals; no runtime allocation) --------
__device__ float g_h   [(size_t)NN * D];  // GEMM output
__device__ float g_agg [(size_t)NN * D];  // layer-2 aggregated output (pool input)
__device__ float g_elu [(size_t)NN * D];  // elu(layer-1 agg) = layer-2 GEMM input
__device__ float g_dinv[NN];              // deg^{-1/2}
__device__ int   g_cnti[NN];              // edge counts per dst
__device__ int   g_off [NN + 1];          // CSR offsets
__device__ int   g_cur [NN];              // fill cursors
__device__ int   g_srcs[EMAX];            // CSR adjacency (src per edge, grouped by dst)
__device__ float g_pool[NG * D];
__device__ float g_cnt [NG];

// ---------------- CSR build ----------------
__global__ void k_zero_cnt() {
    int i = blockIdx.x * blockDim.x + threadIdx.x;
    if (i < NN) g_cnti[i] = 0;
}

__global__ void k_count(const int* __restrict__ ei, int E) {
    int e = blockIdx.x * blockDim.x + threadIdx.x;
    if (e >= E) return;
    unsigned dst = (unsigned)ei[(size_t)E + e];
    if (dst < NN) atomicAdd(&g_cnti[dst], 1);
}

#define SCAN_T 1024
__global__ void k_scan() {   // single block, exclusive scan of g_cnti -> g_off/g_cur
    __shared__ int ssum[SCAN_T];
    int t = threadIdx.x;
    int per = (NN + SCAN_T - 1) / SCAN_T;
    int lo = t * per, hi = lo + per; if (hi > NN) hi = NN;
    int s = 0;
    for (int i = lo; i < hi; i++) s += g_cnti[i];
    ssum[t] = s;
    __syncthreads();
    for (int ofs = 1; ofs < SCAN_T; ofs <<= 1) {
        int v = (t >= ofs) ? ssum[t - ofs] : 0;
        __syncthreads();
        ssum[t] += v;
        __syncthreads();
    }
    int run = (t == 0) ? 0 : ssum[t - 1];
    for (int i = lo; i < hi; i++) {
        int c = g_cnti[i];
        g_off[i] = run; g_cur[i] = run;
        run += c;
    }
    if (t == SCAN_T - 1) g_off[NN] = run;
}

__global__ void k_dinv() {
    int i = blockIdx.x * blockDim.x + threadIdx.x;
    if (i < NN) g_dinv[i] = rsqrtf((float)g_cnti[i] + 1.0f);  // +1 self loop
}

__global__ void k_fill(const int* __restrict__ ei, int E) {
    int e = blockIdx.x * blockDim.x + threadIdx.x;
    if (e >= E) return;
    unsigned src = (unsigned)ei[e];
    unsigned dst = (unsigned)ei[(size_t)E + e];
    if (src >= NN || dst >= NN) return;
    int pos = atomicAdd(&g_cur[dst], 1);
    if (pos < EMAX) g_srcs[pos] = (int)src;
}

// ---------------- tiled GEMM: g_h = X @ W ----------------
#define BM 64
#define BK 64

__device__ __forceinline__
void gemm_body(const float* __restrict__ X, const float* __restrict__ W) {
    __shared__ float sW[BK][128];   // 32 KB
    __shared__ float sX[BM][BK];    // 16 KB

    int tid = threadIdx.x;
    int tm  = tid >> 4;
    int tn  = tid & 15;
    int m0  = blockIdx.x * BM;

    float acc[4][8];
#pragma unroll
    for (int i = 0; i < 4; i++)
#pragma unroll
        for (int j = 0; j < 8; j++) acc[i][j] = 0.f;

    for (int kt = 0; kt < D; kt += BK) {
        {
            const float4* Wg = (const float4*)(W + (size_t)kt * D);
            float4* sWv = (float4*)&sW[0][0];
#pragma unroll
            for (int i = 0; i < 8; i++)
                sWv[tid + 256 * i] = __ldg(&Wg[tid + 256 * i]);
        }
        {
#pragma unroll
            for (int i = 0; i < 4; i++) {
                int idx = tid + 256 * i;
                int r   = idx >> 4;
                int c4  = idx & 15;
                float4 v = make_float4(0.f, 0.f, 0.f, 0.f);
                int row = m0 + r;
                if (row < NN)
                    v = __ldg((const float4*)(X + (size_t)row * D + kt) + c4);
                *(float4*)&sX[r][c4 * 4] = v;
            }
        }
        __syncthreads();

#pragma unroll 8
        for (int k = 0; k < BK; k++) {
            float a0 = sX[tm * 4 + 0][k];
            float a1 = sX[tm * 4 + 1][k];
            float a2 = sX[tm * 4 + 2][k];
            float a3 = sX[tm * 4 + 3][k];
            float4 b0 = *(float4*)&sW[k][tn * 8];
            float4 b1 = *(float4*)&sW[k][tn * 8 + 4];
            acc[0][0] = fmaf(a0, b0.x, acc[0][0]); acc[0][1] = fmaf(a0, b0.y, acc[0][1]);
            acc[0][2] = fmaf(a0, b0.z, acc[0][2]); acc[0][3] = fmaf(a0, b0.w, acc[0][3]);
            acc[0][4] = fmaf(a0, b1.x, acc[0][4]); acc[0][5] = fmaf(a0, b1.y, acc[0][5]);
            acc[0][6] = fmaf(a0, b1.z, acc[0][6]); acc[0][7] = fmaf(a0, b1.w, acc[0][7]);
            acc[1][0] = fmaf(a1, b0.x, acc[1][0]); acc[1][1] = fmaf(a1, b0.y, acc[1][1]);
            acc[1][2] = fmaf(a1, b0.z, acc[1][2]); acc[1][3] = fmaf(a1, b0.w, acc[1][3]);
            acc[1][4] = fmaf(a1, b1.x, acc[1][4]); acc[1][5] = fmaf(a1, b1.y, acc[1][5]);
            acc[1][6] = fmaf(a1, b1.z, acc[1][6]); acc[1][7] = fmaf(a1, b1.w, acc[1][7]);
            acc[2][0] = fmaf(a2, b0.x, acc[2][0]); acc[2][1] = fmaf(a2, b0.y, acc[2][1]);
            acc[2][2] = fmaf(a2, b0.z, acc[2][2]); acc[2][3] = fmaf(a2, b0.w, acc[2][3]);
            acc[2][4] = fmaf(a2, b1.x, acc[2][4]); acc[2][5] = fmaf(a2, b1.y, acc[2][5]);
            acc[2][6] = fmaf(a2, b1.z, acc[2][6]); acc[2][7] = fmaf(a2, b1.w, acc[2][7]);
            acc[3][0] = fmaf(a3, b0.x, acc[3][0]); acc[3][1] = fmaf(a3, b0.y, acc[3][1]);
            acc[3][2] = fmaf(a3, b0.z, acc[3][2]); acc[3][3] = fmaf(a3, b0.w, acc[3][3]);
            acc[3][4] = fmaf(a3, b1.x, acc[3][4]); acc[3][5] = fmaf(a3, b1.y, acc[3][5]);
            acc[3][6] = fmaf(a3, b1.z, acc[3][6]); acc[3][7] = fmaf(a3, b1.w, acc[3][7]);
        }
        __syncthreads();
    }

#pragma unroll
    for (int i = 0; i < 4; i++) {
        int row = m0 + tm * 4 + i;
        if (row >= NN) break;
        float* hp = g_h + (size_t)row * D + tn * 8;
        *(float4*)(hp)     = make_float4(acc[i][0], acc[i][1], acc[i][2], acc[i][3]);
        *(float4*)(hp + 4) = make_float4(acc[i][4], acc[i][5], acc[i][6], acc[i][7]);
    }
}

__global__ __launch_bounds__(256, 2)
void k_gemm_l1(const float* __restrict__ X, const float* __restrict__ W) {
    gemm_body(X, W);
}

__global__ __launch_bounds__(256, 2)
void k_gemm_l2(const float* __restrict__ W) {
    gemm_body(g_elu, W);
}

// ---------------- CSR gather aggregation (warp per node) -----------------
// out[n] = bias + dinv[n] * ( dinv[n]*h[n] + sum_{s in N(n)} dinv[s]*h[s] )
template<bool DO_ELU>
__global__ void k_gather(const float* __restrict__ bias) {
    int node = (blockIdx.x * blockDim.x + threadIdx.x) >> 5;
    int lane = threadIdx.x & 31;
    if (node >= NN) return;

    float dv = g_dinv[node];
    float4 self = __ldg((const float4*)(g_h + (size_t)node * D) + lane);
    float4 acc = make_float4(self.x * dv, self.y * dv, self.z * dv, self.w * dv);

    int j   = g_off[node];
    int end = g_off[node + 1];
    for (; j + 4 <= end; j += 4) {
        int s0 = __ldg(&g_srcs[j + 0]);
        int s1 = __ldg(&g_srcs[j + 1]);
        int s2 = __ldg(&g_srcs[j + 2]);
        int s3 = __ldg(&g_srcs[j + 3]);
        float d0 = __ldg(&g_dinv[s0]);
        float d1 = __ldg(&g_dinv[s1]);
        float d2 = __ldg(&g_dinv[s2]);
        float d3 = __ldg(&g_dinv[s3]);
        float4 v0 = __ldg((const float4*)(g_h + (size_t)s0 * D) + lane);
        float4 v1 = __ldg((const float4*)(g_h + (size_t)s1 * D) + lane);
        float4 v2 = __ldg((const float4*)(g_h + (size_t)s2 * D) + lane);
        float4 v3 = __ldg((const float4*)(g_h + (size_t)s3 * D) + lane);
        acc.x += v0.x * d0 + v1.x * d1 + v2.x * d2 + v3.x * d3;
        acc.y += v0.y * d0 + v1.y * d1 + v2.y * d2 + v3.y * d3;
        acc.z += v0.z * d0 + v1.z * d1 + v2.z * d2 + v3.z * d3;
        acc.w += v0.w * d0 + v1.w * d1 + v2.w * d2 + v3.w * d3;
    }
    for (; j < end; j++) {
        int s = __ldg(&g_srcs[j]);
        float d = __ldg(&g_dinv[s]);
        float4 v = __ldg((const float4*)(g_h + (size_t)s * D) + lane);
        acc.x += v.x * d; acc.y += v.y * d;
        acc.z += v.z * d; acc.w += v.w * d;
    }

    float4 b = __ldg((const float4*)bias + lane);
    acc.x = b.x + dv * acc.x;
    acc.y = b.y + dv * acc.y;
    acc.z = b.z + dv * acc.z;
    acc.w = b.w + dv * acc.w;

    if (DO_ELU) {
        acc.x = acc.x > 0.f ? acc.x : expm1f(acc.x);
        acc.y = acc.y > 0.f ? acc.y : expm1f(acc.y);
        acc.z = acc.z > 0.f ? acc.z : expm1f(acc.z);
        acc.w = acc.w > 0.f ? acc.w : expm1f(acc.w);
        ((float4*)(g_elu + (size_t)node * D))[lane] = acc;
    } else {
        ((float4*)(g_agg + (size_t)node * D))[lane] = acc;
    }
}

// ---------------- pooling ----------------
__global__ void k_zero_pool() {
    int i = blockIdx.x * blockDim.x + threadIdx.x;
    if (i < NG * D) g_pool[i] = 0.f;
    if (i < NG) g_cnt[i] = 0.f;
}

#define NPB 256
__global__ void k_pool(const int* __restrict__ batch) {
    int f = threadIdx.x;
    int start = blockIdx.x * NPB;
    if (start >= NN) return;
    int end = start + NPB; if (end > NN) end = NN;

    float acc = 0.f;
    int cur = batch[start];
    if ((unsigned)cur >= NG) cur = 0;
    for (int n = start; n < end; n++) {
        int b = batch[n];
        if ((unsigned)b >= NG) b = 0;
        if (b != cur) {
            atomicAdd(&g_pool[cur * D + f], acc);
            acc = 0.f; cur = b;
        }
        acc += g_agg[(size_t)n * D + f];
    }
    atomicAdd(&g_pool[cur * D + f], acc);

    if (f == 0) {
        float c = 0.f;
        int cur2 = batch[start];
        if ((unsigned)cur2 >= NG) cur2 = 0;
        for (int n = start; n < end; n++) {
            int b = batch[n];
            if ((unsigned)b >= NG) b = 0;
            if (b != cur2) { atomicAdd(&g_cnt[cur2], c); c = 0.f; cur2 = b; }
            c += 1.0f;
        }
        atomicAdd(&g_cnt[cur2], c);
    }
}

// ---------------- final MLP + log_softmax ----------------
__global__ void k_mlp(const float* __restrict__ fc1W, const float* __restrict__ fc1b,
                      const float* __restrict__ fc2W, const float* __restrict__ fc2b,
                      float* __restrict__ out) {
    int g = blockIdx.x;
    int lane = threadIdx.x;
    __shared__ float mean[D];
    __shared__ float m1[20];
    __shared__ float z[10];
    __shared__ float lse;

    float cnt = fmaxf(g_cnt[g], 1.0f);
    for (int k = lane; k < D; k += 32) mean[k] = g_pool[g * D + k] / cnt;
    __syncwarp();

    if (lane < 20) {
        float s = fc1b[lane];
        for (int k = 0; k < D; k++) s = fmaf(mean[k], fc1W[k * 20 + lane], s);
        m1[lane] = fmaxf(s, 0.0f);
    }
    __syncwarp();

    if (lane < 10) {
        float s = fc2b[lane];
        for (int k = 0; k < 20; k++) s = fmaf(m1[k], fc2W[k * 10 + lane], s);
        z[lane] = s;
    }
    __syncwarp();

    if (lane == 0) {
        float mx = z[0];
        for (int j = 1; j < 10; j++) mx = fmaxf(mx, z[j]);
        float s = 0.f;
        for (int j = 0; j < 10; j++) s += expf(z[j] - mx);
        lse = mx + logf(s);
    }
    __syncwarp();

    if (lane < 10) out[g * 10 + lane] = z[lane] - lse;
}

// ---------------- launch ----------------
extern "C" void kernel_launch(void* const* d_in, const int* in_sizes, int n_in,
                              void* d_out, int out_size) {
    int ix = -1, iei = -1, ib = -1, iW[2] = {-1, -1}, ibias[2] = {-1, -1};
    int if1W = -1, if1b = -1, if2W = -1, if2b = -1;
    int nW = 0, nbias = 0;
    for (int i = 0; i < n_in; i++) {
        int s = in_sizes[i];
        if      (s == NN * D)            ix = i;
        else if (s == NN)                ib = i;
        else if (s == D * D && nW < 2)   iW[nW++] = i;
        else if (s == D && nbias < 2)    ibias[nbias++] = i;
        else if (s == D * 20)            if1W = i;
        else if (s == 20)                if1b = i;
        else if (s == 20 * 10)           if2W = i;
        else if (s == 10)                if2b = i;
        else if (s > NN)                 iei = i;
    }
    bool ok = (ix >= 0 && iei >= 0 && ib >= 0 && nW == 2 && nbias == 2 &&
               if1W >= 0 && if1b >= 0 && if2W >= 0 && if2b >= 0);
    if (!ok) {
        ix = 0; iei = 1; ib = 2; iW[0] = 3; ibias[0] = 4; iW[1] = 5; ibias[1] = 6;
        if1W = 7; if1b = 8; if2W = 9; if2b = 10;
    }

    const float* x     = (const float*)d_in[ix];
    const int*   ei    = (const int*)d_in[iei];
    const int*   batch = (const int*)d_in[ib];
    const float* W1   = (const float*)d_in[iW[0]];
    const float* b1   = (const float*)d_in[ibias[0]];
    const float* W2   = (const float*)d_in[iW[1]];
    const float* b2   = (const float*)d_in[ibias[1]];
    const float* fc1W = (const float*)d_in[if1W];
    const float* fc1b = (const float*)d_in[if1b];
    const float* fc2W = (const float*)d_in[if2W];
    const float* fc2b = (const float*)d_in[if2b];
    float* out = (float*)d_out;

    int E = in_sizes[iei] / 2;

    const int T = 256;
    int nb_nodes  = (NN + T - 1) / T;
    int nb_edges  = (E + T - 1) / T;
    int nb_gemm   = (NN + BM - 1) / BM;
    int nb_gather = (int)(((size_t)NN * 32 + T - 1) / T);
    int nb_pool   = (NN + NPB - 1) / NPB;

    // CSR build + normalization (once, reused by both layers)
    k_zero_cnt<<<nb_nodes, T>>>();
    k_count<<<nb_edges, T>>>(ei, E);
    k_scan<<<1, SCAN_T>>>();
    k_dinv<<<nb_nodes, T>>>();
    k_fill<<<nb_edges, T>>>(ei, E);

    // layer 1
    k_gemm_l1<<<nb_gemm, 256>>>(x, W1);
    k_gather<true><<<nb_gather, T>>>(b1);    // -> g_elu

    // layer 2
    k_gemm_l2<<<nb_gemm, 256>>>(W2);
    k_gather<false><<<nb_gather, T>>>(b2);   // -> g_agg

    // pool + mlp + log_softmax
    k_zero_pool<<<(NG * D + T - 1) / T, T>>>();
    k_pool<<<nb_pool, D>>>(batch);
    k_mlp<<<NG, 32>>>(fc1W, fc1b, fc2W, fc2b, out);
}